// round 10
// baseline (speedup 1.0000x reference)
#include <cuda_runtime.h>
#include <math.h>
#include <stdint.h>

#define ALPHA 0.2f
#define BB   8
#define NN   2048
#define INF  128
#define OUTF 64
#define BN   (BB*NN)   // 16384

#define CHUNKS 32      // chunks per batch for hierarchical scan
#define CROWS  64      // rows per chunk
#define GROUPS 4       // thread groups per chunk CTA (256 threads)
#define GROWS  16      // rows per thread in scan

#define ATT_NPC   32            // nodes per attention CTA
#define ATT_CTAS  (BN/ATT_NPC)  // 512  (bids 0..511: store-bound, start first)
#define SCAN_CTAS (CHUNKS*BB)   // 256  (bids 512..767)

// ---------------- scratch (device globals; no allocation allowed) ----------
__device__ float g_xw [BN*OUTF];          // x_w, original order
__device__ float g_s1 [BN];
__device__ float g_s2 [BN];
__device__ float g_E  [BN];               // exp(s2 - c2), original order
__device__ float g_F  [BN];               // exp(a*s2 - c2), original order
__device__ float g_s2s[BN];               // s2 sorted ascending (per batch)
__device__ int   g_perm[BN];              // sorted rank -> original index
__device__ float g_SXE[BB*(NN+1)*OUTF];   // suffix sums of E*x_w (sorted order)
__device__ float g_PXF[BB*(NN+1)*OUTF];   // prefix sums of F*x_w (exclusive)
__device__ float g_CSE[BB*CHUNKS*OUTF];   // per-chunk vector sums (E)
__device__ float g_CSF[BB*CHUNKS*OUTF];   // per-chunk vector sums (F)
__device__ float g_c2 [BB];
__device__ float g_An [BN];               // A_i * invZ_i
__device__ float g_Bn [BN];               // B_i * invZ_i
__device__ int   g_ki [BN];               // split index per node
__device__ int   g_cnt1[BB];              // scan phase-1 arrival counters
__device__ int   g_cnt2[BB];              // scan phase-2 arrival counters

// ---------------- K1: x_w = inputs @ W ; s1, s2  (16 nodes / CTA) ----------
__global__ void k1_xw(const float* __restrict__ in,
                      const float* __restrict__ emb,
                      const float* __restrict__ W,
                      const float* __restrict__ a)
{
    __shared__ float sW[INF*OUTF];                 // 32 KB
    __shared__ float sa[4*OUTF];                   // 1 KB
    __shared__ __align__(16) float sin_[16][INF];  // 8 KB
    __shared__ float sr1[16][2], sr2[16][2];

    int tid = threadIdx.x;
    // reset mega-kernel counters for this replay (k1 runs first)
    if (blockIdx.x == 0 && tid < BB) { g_cnt1[tid] = 0; g_cnt2[tid] = 0; }

    for (int i = tid; i < INF*OUTF; i += 256) sW[i] = W[i];
    sa[tid] = a[tid];
    int node0 = blockIdx.x * 16;
    {
        const float4* src = (const float4*)(in + (size_t)node0*INF);
        float4* dst = (float4*)&sin_[0][0];
        for (int i = tid; i < 16*INF/4; i += 256) dst[i] = src[i];
    }
    __syncthreads();

    int gq = tid >> 6, f = tid & 63;
    int lane = tid & 31, w2 = (tid >> 5) & 1;

    float acc[4] = {0.f, 0.f, 0.f, 0.f};
#pragma unroll
    for (int kc = 0; kc < INF; kc += 4) {
        float w0 = sW[(kc+0)*OUTF + f];
        float w1 = sW[(kc+1)*OUTF + f];
        float w2v = sW[(kc+2)*OUTF + f];
        float w3 = sW[(kc+3)*OUTF + f];
#pragma unroll
        for (int ng = 0; ng < 4; ng++) {
            float4 s4 = *(const float4*)&sin_[ng*4 + gq][kc];
            acc[ng] = fmaf(s4.x, w0, acc[ng]);
            acc[ng] = fmaf(s4.y, w1, acc[ng]);
            acc[ng] = fmaf(s4.z, w2v, acc[ng]);
            acc[ng] = fmaf(s4.w, w3, acc[ng]);
        }
    }

#pragma unroll
    for (int ng = 0; ng < 4; ng++) {
        int g = ng*4 + gq;
        int node = node0 + g;
        g_xw[(size_t)node*OUTF + f] = acc[ng];

        float e = emb[(size_t)node*OUTF + f];
        float c1 = e*sa[f]       + acc[ng]*sa[64  + f];
        float c2 = e*sa[128 + f] + acc[ng]*sa[192 + f];
#pragma unroll
        for (int o = 16; o > 0; o >>= 1) {
            c1 += __shfl_down_sync(0xffffffffu, c1, o);
            c2 += __shfl_down_sync(0xffffffffu, c2, o);
        }
        if (lane == 0) { sr1[g][w2] = c1; sr2[g][w2] = c2; }
    }
    __syncthreads();
    if (tid < 16) {
        g_s1[node0 + tid] = sr1[tid][0] + sr1[tid][1];
        g_s2[node0 + tid] = sr2[tid][0] + sr2[tid][1];
    }
}

// ---------------- K_rank: counting ranks via BROADCAST compares ------------
// grid (16, BB), 128 threads. Every lane reads the SAME smem address per step
// (broadcast, conflict-free) and compares against its register-held key.
__global__ void k_rank()
{
    __shared__ __align__(16) unsigned long long keys[NN];  // 16 KB
    __shared__ float vals[NN];                              // 8 KB
    __shared__ float red[4];

    int b = blockIdx.y, tid = threadIdx.x;

    float m = -3.4e38f;
    for (int i = tid; i < NN; i += 128) {
        float v = g_s2[b*NN + i];
        vals[i] = v;
        unsigned u = __float_as_uint(v);
        u = u ^ (((unsigned)((int)u >> 31)) | 0x80000000u);  // order-preserving
        keys[i] = ((unsigned long long)u << 11) | (unsigned)i;
        m = fmaxf(m, v);
    }
#pragma unroll
    for (int o = 16; o > 0; o >>= 1)
        m = fmaxf(m, __shfl_xor_sync(0xffffffffu, m, o));
    if ((tid & 31) == 0) red[tid >> 5] = m;
    __syncthreads();
    float c2 = fmaxf(fmaxf(red[0], red[1]), fmaxf(red[2], red[3]));
    if (blockIdx.x == 0 && tid == 0) g_c2[b] = c2;

    int i = blockIdx.x * 128 + tid;
    float x = vals[i];
    g_E[b*NN + i] = expf(x - c2);
    g_F[b*NN + i] = expf(ALPHA*x - c2);

    unsigned long long mykey = keys[i];
    int cnt = 0;
    const ulonglong2* p2 = (const ulonglong2*)keys;
#pragma unroll 8
    for (int j2 = 0; j2 < NN/2; j2++) {
        ulonglong2 kk = p2[j2];          // broadcast: all lanes same address
        cnt += (kk.x < mykey);
        cnt += (kk.y < mykey);
    }
    g_s2s [b*NN + cnt] = x;
    g_perm[b*NN + cnt] = i;
}

// ---------------- k_search: scalar prefix + c1 + search + Z  (grid 4xBB) ---
__global__ void k_search()
{
    __shared__ float s2sl[NN];             // 8 KB
    __shared__ float pE[NN+1], pF[NN+1];   // 16.4 KB
    __shared__ float wsE[16], wsF[16], red[16];
    int b = blockIdx.y, tid = threadIdx.x;
    float c2 = g_c2[b];
    for (int i = tid; i < NN; i += 512) s2sl[i] = g_s2s[b*NN + i];
    __syncthreads();

    float ev[4], fv[4];
    float sE = 0.f, sF = 0.f;
    int base = tid*4;
#pragma unroll
    for (int r = 0; r < 4; r++) {
        float v = s2sl[base + r];
        ev[r] = expf(v - c2); fv[r] = expf(ALPHA*v - c2);
        sE += ev[r]; sF += fv[r];
    }
    float iE = sE, iF = sF;
    int lane = tid & 31, warp = tid >> 5;
#pragma unroll
    for (int o = 1; o < 32; o <<= 1) {
        float tE = __shfl_up_sync(0xffffffffu, iE, o);
        float tF = __shfl_up_sync(0xffffffffu, iF, o);
        if (lane >= o) { iE += tE; iF += tF; }
    }
    if (lane == 31) { wsE[warp] = iE; wsF[warp] = iF; }
    __syncthreads();
    float oE = 0.f, oF = 0.f;
#pragma unroll
    for (int w = 0; w < 16; w++)
        if (w < warp) { oE += wsE[w]; oF += wsF[w]; }
    float rE = oE + iE - sE, rF = oF + iF - sF;   // exclusive offsets
#pragma unroll
    for (int r = 0; r < 4; r++) {
        pE[base + r] = rE; pF[base + r] = rF;
        rE += ev[r]; rF += fv[r];
    }
    if (tid == 511) { pE[NN] = rE; pF[NN] = rF; }

    // c1 = max over s1
    float m = -3.4e38f;
    for (int i = tid; i < NN; i += 512) m = fmaxf(m, g_s1[b*NN + i]);
#pragma unroll
    for (int o = 16; o > 0; o >>= 1)
        m = fmaxf(m, __shfl_xor_sync(0xffffffffu, m, o));
    if (lane == 0) red[warp] = m;
    __syncthreads();                  // also covers pE/pF writes above
    float c1 = red[0];
#pragma unroll
    for (int w = 1; w < 16; w++) c1 = fmaxf(c1, red[w]);
    float totE = pE[NN];

    int node = b*NN + blockIdx.x*512 + tid;
    float s1 = g_s1[node];
    float t = -s1;
    int lo = 0, hi = NN;
    while (lo < hi) { int mid = (lo + hi) >> 1; if (s2sl[mid] < t) lo = mid + 1; else hi = mid; }
    int k = lo;
    float A  = expf(s1 - c1);
    float Bv = expf(ALPHA*s1 - c1);
    float Z  = A * (totE - pE[k]) + Bv * pF[k];
    float invZ = 1.0f / Z;
    g_An[node] = A * invZ;
    g_Bn[node] = Bv * invZ;
    g_ki[node] = k;
}

// ---------------- k_mega: fused attention + scan + h_prime -----------------
// 256 threads/CTA -> 8 CTAs/SM -> all 768 CTAs in ONE wave. Attention CTAs
// take the low bids (store-bound, no waiting); scan CTAs overlap behind them.
struct ScanSmem {
    float Es[CROWS], Fs[CROWS];
    int   pm[CROWS];
    float psE[GROUPS][OUTF], psF[GROUPS][OUTF];
    float sCSE[CHUNKS][OUTF], sCSF[CHUNKS][OUTF];
};
struct AttSmem {
    float sE[NN], sF[NN], ss2[NN];
    float sAn[ATT_NPC], sBn[ATT_NPC], sT[ATT_NPC];
};

__global__ __launch_bounds__(256) void k_mega(float* __restrict__ out_h,
                                              float* __restrict__ out_att)
{
    __shared__ __align__(16) char smem_raw[
        sizeof(AttSmem) > sizeof(ScanSmem) ? sizeof(AttSmem) : sizeof(ScanSmem)];
    int bid = blockIdx.x;
    int tid = threadIdx.x;

    if (bid < ATT_CTAS) {
        // ================= attention role: 32 nodes =================
        AttSmem& A = *reinterpret_cast<AttSmem*>(smem_raw);
        int i0 = bid * ATT_NPC;
        int b = i0 >> 11;
        {
            const float4* pe = (const float4*)(g_E  + b*NN);
            const float4* pf = (const float4*)(g_F  + b*NN);
            const float4* ps = (const float4*)(g_s2 + b*NN);
            float4* de = (float4*)A.sE; float4* df = (float4*)A.sF; float4* ds = (float4*)A.ss2;
            for (int i = tid; i < NN/4; i += 256) { de[i] = pe[i]; df[i] = pf[i]; ds[i] = ps[i]; }
        }
        if (tid < ATT_NPC) {
            int node = i0 + tid;
            A.sAn[tid] = g_An[node]; A.sBn[tid] = g_Bn[node];
            A.sT[tid]  = -g_s1[node];
        }
        __syncthreads();

#pragma unroll
        for (int jj = 0; jj < 2; jj++) {
            int j4 = tid + jj*256;
            float4 e4 = ((const float4*)A.sE)[j4];
            float4 f4 = ((const float4*)A.sF)[j4];
            float4 s4 = ((const float4*)A.ss2)[j4];
            float* outbase = out_att + (size_t)i0 * NN + j4*4;
#pragma unroll
            for (int g = 0; g < ATT_NPC; g++) {
                float Ai = A.sAn[g], Bi = A.sBn[g], t = A.sT[g];
                float4 o;
                o.x = (s4.x >= t) ? Ai*e4.x : Bi*f4.x;
                o.y = (s4.y >= t) ? Ai*e4.y : Bi*f4.y;
                o.z = (s4.z >= t) ? Ai*e4.z : Bi*f4.z;
                o.w = (s4.w >= t) ? Ai*e4.w : Bi*f4.w;
                *(float4*)(outbase + (size_t)g*NN) = o;
            }
        }
    } else {
        // ================= scan role: chunk c of batch b =================
        ScanSmem& S = *reinterpret_cast<ScanSmem*>(smem_raw);
        int sbid = bid - ATT_CTAS;
        int b = sbid >> 5, c = sbid & 31;
        float c2 = g_c2[b];
        if (tid < CROWS) {
            float v = g_s2s[b*NN + c*CROWS + tid];
            S.Es[tid] = expf(v - c2);
            S.Fs[tid] = expf(ALPHA*v - c2);
            S.pm[tid] = g_perm[b*NN + c*CROWS + tid];
        }
        __syncthreads();
        int g = tid >> 6, f = tid & 63;
        const float* xw = g_xw + (size_t)b*NN*OUTF;
        float aE = 0.f, aF = 0.f;
        float xr[GROWS];
        int r0 = g * GROWS;
#pragma unroll
        for (int r = r0; r < r0 + GROWS; r++) {
            float x = xw[(size_t)S.pm[r]*OUTF + f];
            xr[r - r0] = x;
            aE = fmaf(S.Es[r], x, aE);
            aF = fmaf(S.Fs[r], x, aF);
        }
        S.psE[g][f] = aE; S.psF[g][f] = aF;
        __syncthreads();
        if (tid < OUTF) {
            float s = 0.f;
#pragma unroll
            for (int gg = 0; gg < GROUPS; gg++) s += S.psE[gg][tid];
            g_CSE[(b*CHUNKS + c)*OUTF + tid] = s;
        } else if (tid < 2*OUTF) {
            int ff = tid - OUTF;
            float s = 0.f;
#pragma unroll
            for (int gg = 0; gg < GROUPS; gg++) s += S.psF[gg][ff];
            g_CSF[(b*CHUNKS + c)*OUTF + ff] = s;
        }
        // phase-1 barrier across this batch's 32 chunk CTAs
        __threadfence();
        __syncthreads();
        if (tid == 0) {
            atomicAdd(&g_cnt1[b], 1);
            while (atomicAdd(&g_cnt1[b], 0) < CHUNKS) {}
        }
        __syncthreads();

        // stage all chunk sums (coalesced)
        for (int i = tid; i < CHUNKS*OUTF; i += 256) {
            (&S.sCSE[0][0])[i] = g_CSE[b*CHUNKS*OUTF + i];
            (&S.sCSF[0][0])[i] = g_CSF[b*CHUNKS*OUTF + i];
        }
        __syncthreads();

        float offE = 0.f, offF = 0.f, totE = 0.f;
#pragma unroll
        for (int cc = 0; cc < CHUNKS; cc++) {
            float vE = S.sCSE[cc][f];
            float vF = S.sCSF[cc][f];
            totE += vE;
            if (cc < c) { offE += vE; offF += vF; }
        }
#pragma unroll
        for (int gg = 0; gg < GROUPS-1; gg++)
            if (gg < g) { offE += S.psE[gg][f]; offF += S.psF[gg][f]; }

        float* SXE = g_SXE + (size_t)b*(NN+1)*OUTF;
        float* PXF = g_PXF + (size_t)b*(NN+1)*OUTF;
        float runE = offE, runF = offF;
#pragma unroll
        for (int r = r0; r < r0 + GROWS; r++) {
            int R = c*CROWS + r;
            float x = xr[r - r0];
            SXE[(size_t)R*OUTF + f] = totE - runE;
            runE = fmaf(S.Es[r], x, runE);
            runF = fmaf(S.Fs[r], x, runF);
            PXF[(size_t)(R+1)*OUTF + f] = runF;
        }
        if (c == CHUNKS-1 && tid < OUTF) SXE[(size_t)NN*OUTF + tid] = 0.f;
        if (c == 0 && tid < OUTF)        PXF[tid] = 0.f;

        // phase-2 barrier, then h_prime for this chunk's 64 nodes
        __threadfence();
        __syncthreads();
        if (tid == 0) {
            atomicAdd(&g_cnt2[b], 1);
            while (atomicAdd(&g_cnt2[b], 0) < CHUNKS) {}
        }
        __syncthreads();

#pragma unroll
        for (int e = tid; e < CROWS*OUTF; e += 256) {
            int gg = e >> 6, ff = e & 63;
            int node = b*NN + c*CROWS + gg;
            int k = g_ki[node];
            size_t basebk = ((size_t)b*(NN+1) + k)*OUTF + ff;
            float h = g_An[node]*g_SXE[basebk] + g_Bn[node]*g_PXF[basebk];
            out_h[(size_t)node*OUTF + ff] = fmaxf(h, 0.f);
        }
    }
}

// ---------------- launch ----------------------------------------------------
extern "C" void kernel_launch(void* const* d_in, const int* in_sizes, int n_in,
                              void* d_out, int out_size)
{
    const float* in  = (const float*)d_in[0];   // (8,2048,128)
    const float* emb = (const float*)d_in[1];   // (8,2048,64)
    const float* W   = (const float*)d_in[2];   // (128,64)
    const float* a   = (const float*)d_in[3];   // (256,1)

    float* out    = (float*)d_out;
    float* out_h  = out;                          // relu(h_prime): BN*OUTF
    float* out_at = out + (size_t)BN*OUTF;        // attention:     BN*NN

    k1_xw   <<<BN/16,               256>>>(in, emb, W, a);
    k_rank  <<<dim3(16,BB),         128>>>();
    k_search<<<dim3(4,BB),          512>>>();
    k_mega  <<<ATT_CTAS + SCAN_CTAS,256>>>(out_h, out_at);
}

// round 12
// speedup vs baseline: 1.1597x; 1.1597x over previous
#include <cuda_runtime.h>
#include <math.h>
#include <stdint.h>

#define ALPHA 0.2f
#define BB   8
#define NN   2048
#define INF  128
#define OUTF 64
#define BN   (BB*NN)   // 16384

#define CHUNKS 32      // chunks per batch for hierarchical scan
#define CROWS  64      // rows per chunk
#define GROUPS 8       // thread groups per chunk CTA (512 threads)
#define GROWS  8       // rows per thread in scan

#define SCAN_CTAS (CHUNKS*BB)   // 256 (low bids: all resident in wave 1)
#define ATT_NPC   32            // nodes per attention CTA
#define ATT_CTAS  (BN/ATT_NPC)  // 512

// ---------------- scratch (device globals; no allocation allowed) ----------
__device__ float g_xw [BN*OUTF];          // x_w, original order
__device__ float g_s1 [BN];
__device__ float g_s2 [BN];
__device__ float g_E  [BN];               // exp(s2 - c2), original order
__device__ float g_F  [BN];               // exp(a*s2 - c2), original order
__device__ float g_s2s[BN];               // s2 sorted ascending (per batch)
__device__ int   g_perm[BN];              // sorted rank -> original index
__device__ float g_CSE[BB*CHUNKS*OUTF];   // per-chunk vector sums (E)
__device__ float g_CSF[BB*CHUNKS*OUTF];   // per-chunk vector sums (F)
__device__ float g_c2 [BB];
__device__ float g_An [BN];               // A_i * invZ_i
__device__ float g_Bn [BN];               // B_i * invZ_i
__device__ int   g_ki [BN];               // split index per node
__device__ int   g_cnt1[BB];              // scan phase-1 arrival counters

// ---------------- K1: x_w = inputs @ W ; s1, s2  (16 nodes / CTA) ----------
__global__ void k1_xw(const float* __restrict__ in,
                      const float* __restrict__ emb,
                      const float* __restrict__ W,
                      const float* __restrict__ a)
{
    __shared__ float sW[INF*OUTF];                 // 32 KB
    __shared__ float sa[4*OUTF];                   // 1 KB
    __shared__ __align__(16) float sin_[16][INF];  // 8 KB
    __shared__ float sr1[16][2], sr2[16][2];

    int tid = threadIdx.x;
    // reset mega-kernel counters for this replay (k1 runs first)
    if (blockIdx.x == 0 && tid < BB) g_cnt1[tid] = 0;

    for (int i = tid; i < INF*OUTF; i += 256) sW[i] = W[i];
    sa[tid] = a[tid];
    int node0 = blockIdx.x * 16;
    {
        const float4* src = (const float4*)(in + (size_t)node0*INF);
        float4* dst = (float4*)&sin_[0][0];
        for (int i = tid; i < 16*INF/4; i += 256) dst[i] = src[i];
    }
    __syncthreads();

    int gq = tid >> 6, f = tid & 63;
    int lane = tid & 31, w2 = (tid >> 5) & 1;

    float acc[4] = {0.f, 0.f, 0.f, 0.f};
#pragma unroll
    for (int kc = 0; kc < INF; kc += 4) {
        float w0 = sW[(kc+0)*OUTF + f];
        float w1 = sW[(kc+1)*OUTF + f];
        float w2v = sW[(kc+2)*OUTF + f];
        float w3 = sW[(kc+3)*OUTF + f];
#pragma unroll
        for (int ng = 0; ng < 4; ng++) {
            float4 s4 = *(const float4*)&sin_[ng*4 + gq][kc];
            acc[ng] = fmaf(s4.x, w0, acc[ng]);
            acc[ng] = fmaf(s4.y, w1, acc[ng]);
            acc[ng] = fmaf(s4.z, w2v, acc[ng]);
            acc[ng] = fmaf(s4.w, w3, acc[ng]);
        }
    }

#pragma unroll
    for (int ng = 0; ng < 4; ng++) {
        int g = ng*4 + gq;
        int node = node0 + g;
        g_xw[(size_t)node*OUTF + f] = acc[ng];

        float e = emb[(size_t)node*OUTF + f];
        float c1 = e*sa[f]       + acc[ng]*sa[64  + f];
        float c2 = e*sa[128 + f] + acc[ng]*sa[192 + f];
#pragma unroll
        for (int o = 16; o > 0; o >>= 1) {
            c1 += __shfl_down_sync(0xffffffffu, c1, o);
            c2 += __shfl_down_sync(0xffffffffu, c2, o);
        }
        if (lane == 0) { sr1[g][w2] = c1; sr2[g][w2] = c2; }
    }
    __syncthreads();
    if (tid < 16) {
        g_s1[node0 + tid] = sr1[tid][0] + sr1[tid][1];
        g_s2[node0 + tid] = sr2[tid][0] + sr2[tid][1];
    }
}

// ---------------- K_rank: counting ranks via broadcast compares ------------
__global__ void k_rank()
{
    __shared__ __align__(16) unsigned long long keys[NN];  // 16 KB
    __shared__ float vals[NN];                              // 8 KB
    __shared__ float red[4];

    int b = blockIdx.y, tid = threadIdx.x;

    float m = -3.4e38f;
    for (int i = tid; i < NN; i += 128) {
        float v = g_s2[b*NN + i];
        vals[i] = v;
        unsigned u = __float_as_uint(v);
        u = u ^ (((unsigned)((int)u >> 31)) | 0x80000000u);  // order-preserving
        keys[i] = ((unsigned long long)u << 11) | (unsigned)i;
        m = fmaxf(m, v);
    }
#pragma unroll
    for (int o = 16; o > 0; o >>= 1)
        m = fmaxf(m, __shfl_xor_sync(0xffffffffu, m, o));
    if ((tid & 31) == 0) red[tid >> 5] = m;
    __syncthreads();
    float c2 = fmaxf(fmaxf(red[0], red[1]), fmaxf(red[2], red[3]));
    if (blockIdx.x == 0 && tid == 0) g_c2[b] = c2;

    int i = blockIdx.x * 128 + tid;
    float x = vals[i];
    g_E[b*NN + i] = expf(x - c2);
    g_F[b*NN + i] = expf(ALPHA*x - c2);

    unsigned long long mykey = keys[i];
    int cnt = 0;
    const ulonglong2* p2 = (const ulonglong2*)keys;
#pragma unroll 8
    for (int j2 = 0; j2 < NN/2; j2++) {
        ulonglong2 kk = p2[j2];          // broadcast: all lanes same address
        cnt += (kk.x < mykey);
        cnt += (kk.y < mykey);
    }
    g_s2s [b*NN + cnt] = x;
    g_perm[b*NN + cnt] = i;
}

// ---------------- k_search: scalar prefix + c1 + search + Z  (grid 4xBB) ---
__global__ void k_search()
{
    __shared__ float s2sl[NN];             // 8 KB
    __shared__ float pE[NN+1], pF[NN+1];   // 16.4 KB
    __shared__ float wsE[16], wsF[16], red[16];
    int b = blockIdx.y, tid = threadIdx.x;
    float c2 = g_c2[b];
    for (int i = tid; i < NN; i += 512) s2sl[i] = g_s2s[b*NN + i];
    __syncthreads();

    float ev[4], fv[4];
    float sE = 0.f, sF = 0.f;
    int base = tid*4;
#pragma unroll
    for (int r = 0; r < 4; r++) {
        float v = s2sl[base + r];
        ev[r] = expf(v - c2); fv[r] = expf(ALPHA*v - c2);
        sE += ev[r]; sF += fv[r];
    }
    float iE = sE, iF = sF;
    int lane = tid & 31, warp = tid >> 5;
#pragma unroll
    for (int o = 1; o < 32; o <<= 1) {
        float tE = __shfl_up_sync(0xffffffffu, iE, o);
        float tF = __shfl_up_sync(0xffffffffu, iF, o);
        if (lane >= o) { iE += tE; iF += tF; }
    }
    if (lane == 31) { wsE[warp] = iE; wsF[warp] = iF; }
    __syncthreads();
    float oE = 0.f, oF = 0.f;
#pragma unroll
    for (int w = 0; w < 16; w++)
        if (w < warp) { oE += wsE[w]; oF += wsF[w]; }
    float rE = oE + iE - sE, rF = oF + iF - sF;   // exclusive offsets
#pragma unroll
    for (int r = 0; r < 4; r++) {
        pE[base + r] = rE; pF[base + r] = rF;
        rE += ev[r]; rF += fv[r];
    }
    if (tid == 511) { pE[NN] = rE; pF[NN] = rF; }

    // c1 = max over s1
    float m = -3.4e38f;
    for (int i = tid; i < NN; i += 512) m = fmaxf(m, g_s1[b*NN + i]);
#pragma unroll
    for (int o = 16; o > 0; o >>= 1)
        m = fmaxf(m, __shfl_xor_sync(0xffffffffu, m, o));
    if (lane == 0) red[warp] = m;
    __syncthreads();                  // also covers pE/pF writes above
    float c1 = red[0];
#pragma unroll
    for (int w = 1; w < 16; w++) c1 = fmaxf(c1, red[w]);
    float totE = pE[NN];

    int node = b*NN + blockIdx.x*512 + tid;
    float s1 = g_s1[node];
    float t = -s1;
    int lo = 0, hi = NN;
    while (lo < hi) { int mid = (lo + hi) >> 1; if (s2sl[mid] < t) lo = mid + 1; else hi = mid; }
    int k = lo;
    float A  = expf(s1 - c1);
    float Bv = expf(ALPHA*s1 - c1);
    float Z  = A * (totE - pE[k]) + Bv * pF[k];
    float invZ = 1.0f / Z;
    g_An[node] = A * invZ;
    g_Bn[node] = Bv * invZ;
    g_ki[node] = k;
}

// ---------------- k_mega: fused scan (smem slice) + h_prime + attention ----
// 512 threads. Scan CTAs never write SXE/PXF to DRAM: the per-chunk slice
// stays in smem and the CTA writes h_prime for nodes whose k lands in it.
struct ScanSmem {
    float Es[CROWS], Fs[CROWS];
    int   pm[CROWS];
    float psE[GROUPS][OUTF], psF[GROUPS][OUTF];
    union {
        struct { float sCSE[CHUNKS][OUTF], sCSF[CHUNKS][OUTF]; } cs;   // 16 KB
        struct { float sSXE[CROWS+1][OUTF], sPXF[CROWS+1][OUTF]; } sl; // 32.5 KB
    } u;
};
struct AttSmem {
    float sE[NN], sF[NN], ss2[NN];
    float sAn[ATT_NPC], sBn[ATT_NPC], sT[ATT_NPC];
};

__global__ __launch_bounds__(512) void k_mega(float* __restrict__ out_h,
                                              float* __restrict__ out_att)
{
    __shared__ __align__(16) char smem_raw[
        sizeof(AttSmem) > sizeof(ScanSmem) ? sizeof(AttSmem) : sizeof(ScanSmem)];
    int bid = blockIdx.x;
    int tid = threadIdx.x;

    if (bid < SCAN_CTAS) {
        // ================= scan role: chunk c of batch b =================
        ScanSmem& S = *reinterpret_cast<ScanSmem*>(smem_raw);
        int b = bid >> 5, c = bid & 31;
        float c2 = g_c2[b];
        if (tid < CROWS) {
            float v = g_s2s[b*NN + c*CROWS + tid];
            S.Es[tid] = expf(v - c2);
            S.Fs[tid] = expf(ALPHA*v - c2);
            S.pm[tid] = g_perm[b*NN + c*CROWS + tid];
        }
        __syncthreads();
        int g = tid >> 6, f = tid & 63;
        const float* xw = g_xw + (size_t)b*NN*OUTF;
        float aE = 0.f, aF = 0.f;
        float xr[GROWS];
        int r0 = g * GROWS;
#pragma unroll
        for (int r = r0; r < r0 + GROWS; r++) {
            float x = xw[(size_t)S.pm[r]*OUTF + f];
            xr[r - r0] = x;
            aE = fmaf(S.Es[r], x, aE);
            aF = fmaf(S.Fs[r], x, aF);
        }
        S.psE[g][f] = aE; S.psF[g][f] = aF;
        __syncthreads();
        if (tid < OUTF) {
            float s = 0.f;
#pragma unroll
            for (int gg = 0; gg < GROUPS; gg++) s += S.psE[gg][tid];
            g_CSE[(b*CHUNKS + c)*OUTF + tid] = s;
        } else if (tid < 2*OUTF) {
            int ff = tid - OUTF;
            float s = 0.f;
#pragma unroll
            for (int gg = 0; gg < GROUPS; gg++) s += S.psF[gg][ff];
            g_CSF[(b*CHUNKS + c)*OUTF + ff] = s;
        }
        // phase-1 barrier across this batch's 32 chunk CTAs
        __threadfence();
        __syncthreads();
        if (tid == 0) {
            atomicAdd(&g_cnt1[b], 1);
            while (atomicAdd(&g_cnt1[b], 0) < CHUNKS) {}
        }
        __syncthreads();

        // stage all chunk sums (coalesced)
        for (int i = tid; i < CHUNKS*OUTF; i += 512) {
            (&S.u.cs.sCSE[0][0])[i] = g_CSE[b*CHUNKS*OUTF + i];
            (&S.u.cs.sCSF[0][0])[i] = g_CSF[b*CHUNKS*OUTF + i];
        }
        __syncthreads();

        float offE = 0.f, offF = 0.f, totE = 0.f;
#pragma unroll
        for (int cc = 0; cc < CHUNKS; cc++) {
            float vE = S.u.cs.sCSE[cc][f];
            float vF = S.u.cs.sCSF[cc][f];
            totE += vE;
            if (cc < c) { offE += vE; offF += vF; }
        }
#pragma unroll
        for (int gg = 0; gg < GROUPS-1; gg++)
            if (gg < g) { offE += S.psE[gg][f]; offF += S.psF[gg][f]; }
        __syncthreads();   // everyone done reading cs before slice overwrite

        // final scan -> smem slice (local k = c*64 .. c*64+64)
        float runE = offE, runF = offF;
#pragma unroll
        for (int r = r0; r < r0 + GROWS; r++) {
            S.u.sl.sSXE[r][f] = totE - runE;    // SXE at rank c*64+r
            S.u.sl.sPXF[r][f] = runF;           // exclusive prefix at c*64+r
            float x = xr[r - r0];
            runE = fmaf(S.Es[r], x, runE);
            runF = fmaf(S.Fs[r], x, runF);
        }
        if (g == GROUPS-1) {
            S.u.sl.sSXE[CROWS][f] = totE - runE;
            S.u.sl.sPXF[CROWS][f] = runF;
        }
        __syncthreads();

        // h_prime for nodes whose ki lies in this chunk
        int kLo = c*CROWS, kHi = kLo + CROWS;
        bool last = (c == CHUNKS-1);
        for (int i = tid; i < NN; i += 512) {
            int node = b*NN + i;
            int k = g_ki[node];
            if ((k >= kLo && k < kHi) || (last && k == NN)) {
                int kl = k - kLo;
                float An = g_An[node], Bn = g_Bn[node];
                float* dst = out_h + (size_t)node*OUTF;
#pragma unroll
                for (int ff = 0; ff < OUTF; ff += 4) {
                    float4 hv;
                    hv.x = fmaxf(An*S.u.sl.sSXE[kl][ff+0] + Bn*S.u.sl.sPXF[kl][ff+0], 0.f);
                    hv.y = fmaxf(An*S.u.sl.sSXE[kl][ff+1] + Bn*S.u.sl.sPXF[kl][ff+1], 0.f);
                    hv.z = fmaxf(An*S.u.sl.sSXE[kl][ff+2] + Bn*S.u.sl.sPXF[kl][ff+2], 0.f);
                    hv.w = fmaxf(An*S.u.sl.sSXE[kl][ff+3] + Bn*S.u.sl.sPXF[kl][ff+3], 0.f);
                    *(float4*)(dst + ff) = hv;
                }
            }
        }
    } else {
        // ================= attention role: 32 nodes =================
        AttSmem& A = *reinterpret_cast<AttSmem*>(smem_raw);
        int abid = bid - SCAN_CTAS;          // 0..511
        int i0 = abid * ATT_NPC;
        int b = i0 >> 11;
        {
            const float4* pe = (const float4*)(g_E  + b*NN);
            const float4* pf = (const float4*)(g_F  + b*NN);
            const float4* ps = (const float4*)(g_s2 + b*NN);
            float4* de = (float4*)A.sE; float4* df = (float4*)A.sF; float4* ds = (float4*)A.ss2;
            for (int i = tid; i < NN/4; i += 512) { de[i] = pe[i]; df[i] = pf[i]; ds[i] = ps[i]; }
        }
        if (tid < ATT_NPC) {
            int node = i0 + tid;
            A.sAn[tid] = g_An[node]; A.sBn[tid] = g_Bn[node];
            A.sT[tid]  = -g_s1[node];
        }
        __syncthreads();

        int j4 = tid;                         // exactly NN/4 == 512 columns
        float4 e4 = ((const float4*)A.sE)[j4];
        float4 f4 = ((const float4*)A.sF)[j4];
        float4 s4 = ((const float4*)A.ss2)[j4];
        float* outbase = out_att + (size_t)i0 * NN + j4*4;
#pragma unroll
        for (int g = 0; g < ATT_NPC; g++) {
            float Ai = A.sAn[g], Bi = A.sBn[g], t = A.sT[g];
            float4 o;
            o.x = (s4.x >= t) ? Ai*e4.x : Bi*f4.x;
            o.y = (s4.y >= t) ? Ai*e4.y : Bi*f4.y;
            o.z = (s4.z >= t) ? Ai*e4.z : Bi*f4.z;
            o.w = (s4.w >= t) ? Ai*e4.w : Bi*f4.w;
            *(float4*)(outbase + (size_t)g*NN) = o;
        }
    }
}

// ---------------- launch ----------------------------------------------------
extern "C" void kernel_launch(void* const* d_in, const int* in_sizes, int n_in,
                              void* d_out, int out_size)
{
    const float* in  = (const float*)d_in[0];   // (8,2048,128)
    const float* emb = (const float*)d_in[1];   // (8,2048,64)
    const float* W   = (const float*)d_in[2];   // (128,64)
    const float* a   = (const float*)d_in[3];   // (256,1)

    float* out    = (float*)d_out;
    float* out_h  = out;                          // relu(h_prime): BN*OUTF
    float* out_at = out + (size_t)BN*OUTF;        // attention:     BN*NN

    k1_xw   <<<BN/16,               256>>>(in, emb, W, a);
    k_rank  <<<dim3(16,BB),         128>>>();
    k_search<<<dim3(4,BB),          512>>>();
    k_mega  <<<SCAN_CTAS + ATT_CTAS,512>>>(out_h, out_at);
}